// round 17
// baseline (speedup 1.0000x reference)
#include <cuda_runtime.h>
#include <cuda_fp16.h>
#include <math.h>
#include <stdint.h>

// Problem dims
#define BB   128
#define TT   512
#define FF   784
#define HH   256
#define NG   1024   // 4*H
#define CC   10
#define BN_EPS 1e-3f

// K1 GEMM tiling: BK=32, K padded to 800
#define KP    800
#define NCHK2 (KP / 32)   // 25

// Scratch (device globals; no runtime allocation allowed)
__device__ float  g_xw[(size_t)BB * TT * NG];    // 256 MiB
__device__ float  g_hs[(size_t)BB * TT * HH];    //  64 MiB
__device__ float4 g_rw[(size_t)HH * HH];         //   1 MiB packed rec weights {i,f,c,o}
__device__ __half g_bhi[(size_t)NG * KP];        // 1.6 MiB: kernel^T hi [n][k] fp16
__device__ __half g_blo[(size_t)NG * KP];        // 1.6 MiB: kernel^T lo
__device__ __half g_ah [(size_t)BB * TT * KP];   // 105 MiB: x fp16 [m][k]

// ---------------------------------------------------------------------------
// helpers
// ---------------------------------------------------------------------------
__device__ __forceinline__ uint32_t smem_u32(const void* p) {
    uint32_t a;
    asm("{ .reg .u64 t; cvta.to.shared.u64 t, %1; cvt.u32.u64 %0, t; }" : "=r"(a) : "l"(p));
    return a;
}
__device__ __forceinline__ float fsig(float x) {
    return __fdividef(1.f, 1.f + __expf(-x));
}
__device__ __forceinline__ float ftanh(float x) {
    x = fminf(fmaxf(x, -15.f), 15.f);
    float e = __expf(-2.f * x);
    return __fdividef(1.f - e, 1.f + e);
}
__device__ __forceinline__ void mma_f16(float* d, const uint32_t* a, const uint32_t* b) {
    asm volatile(
        "mma.sync.aligned.m16n8k16.row.col.f32.f16.f16.f32 "
        "{%0,%1,%2,%3}, {%4,%5,%6,%7}, {%8,%9}, {%0,%1,%2,%3};"
        : "+f"(d[0]), "+f"(d[1]), "+f"(d[2]), "+f"(d[3])
        : "r"(a[0]), "r"(a[1]), "r"(a[2]), "r"(a[3]), "r"(b[0]), "r"(b[1]));
}
__device__ __forceinline__ void ldsm4(uint32_t* r, uint32_t a) {
    asm volatile("ldmatrix.sync.aligned.m8n8.x4.shared.b16 {%0,%1,%2,%3}, [%4];"
                 : "=r"(r[0]), "=r"(r[1]), "=r"(r[2]), "=r"(r[3]) : "r"(a));
}
// packed fp32x2 (B300 FFMA2)
__device__ __forceinline__ void ffma2(unsigned long long& d,
                                      unsigned long long a, unsigned long long b) {
    asm("fma.rn.f32x2 %0, %1, %2, %0;" : "+l"(d) : "l"(a), "l"(b));
}
__device__ __forceinline__ unsigned long long addx2(unsigned long long a,
                                                    unsigned long long b) {
    unsigned long long d;
    asm("add.rn.f32x2 %0, %1, %2;" : "=l"(d) : "l"(a), "l"(b));
    return d;
}
__device__ __forceinline__ unsigned long long shflx2(unsigned long long v, int m) {
    uint32_t lo = (uint32_t)v, hi = (uint32_t)(v >> 32);
    lo = __shfl_xor_sync(0xffffffffu, lo, m);
    hi = __shfl_xor_sync(0xffffffffu, hi, m);
    return ((unsigned long long)hi << 32) | lo;
}
__device__ __forceinline__ float lof(unsigned long long v) {
    return __uint_as_float((uint32_t)v);
}
__device__ __forceinline__ float hif(unsigned long long v) {
    return __uint_as_float((uint32_t)(v >> 32));
}
__device__ __forceinline__ void cp16(uint32_t dst, const void* src) {
    asm volatile("cp.async.cg.shared.global [%0], [%1], 16;" :: "r"(dst), "l"(src));
}
#define CP_COMMIT() asm volatile("cp.async.commit_group;" ::: "memory")
#define CP_WAIT1()  asm volatile("cp.async.wait_group 1;"  ::: "memory")

// ---------------------------------------------------------------------------
// K0a: pack rec_kernel [H,4H] -> rw[k][u] float4 {i,f,c,o}
// ---------------------------------------------------------------------------
__global__ void pack_rec_kernel(const float* __restrict__ rec, float4* __restrict__ rw)
{
    int idx = blockIdx.x * blockDim.x + threadIdx.x;
    if (idx >= HH * HH) return;
    int k = idx >> 8;
    int u = idx & 255;
    const float* r = rec + (size_t)k * NG;
    rw[idx] = make_float4(r[u], r[HH + u], r[2 * HH + u], r[3 * HH + u]);
}

// ---------------------------------------------------------------------------
// K0b: split + transpose kernel [F,4H] -> g_bhi/g_blo [n][k<KP] fp16 hi/lo
// ---------------------------------------------------------------------------
__global__ void pack_b_kernel(const float* __restrict__ Bm)
{
    int idx = blockIdx.x * blockDim.x + threadIdx.x;
    if (idx >= NG * KP) return;
    int n = idx / KP;
    int k = idx % KP;
    float v = (k < FF) ? Bm[(size_t)k * NG + n] : 0.f;
    __half h = __float2half(v);
    __half l = __float2half(v - __half2float(h));
    g_bhi[idx] = h;
    g_blo[idx] = l;
}

// ---------------------------------------------------------------------------
// K0c: x [m][k<FF] fp32 -> g_ah [m][k<KP] fp16 (zero-padded)
// ---------------------------------------------------------------------------
__global__ void pack_a_kernel(const float* __restrict__ x)
{
    size_t idx = (size_t)blockIdx.x * blockDim.x + threadIdx.x;
    if (idx >= (size_t)BB * TT * KP) return;
    size_t m = idx / KP;
    int k = (int)(idx % KP);
    g_ah[idx] = __float2half(k < FF ? x[m * FF + k] : 0.f);
}

// ---------------------------------------------------------------------------
// K1: xw = x @ kernel + bias via mma.sync fp16x2: a*(b_hi + b_lo).
// BK=32 (25 chunks), 3-stage cp.async pipeline, ldmatrix.x4 fragments.
// smem/stage: A 10240 | Bh 10240 | Bl 10240 (rows 64B data + 16B pad).
// ---------------------------------------------------------------------------
#define SROW 80
#define K1_ARR_BYTES   (128 * SROW)                  // 10240
#define K1_STAGE_BYTES (3 * K1_ARR_BYTES)            // 30720
#define K1_SMEM        (3 * K1_STAGE_BYTES)          // 92160

__global__ __launch_bounds__(256, 2)
void gemm_mma_kernel(const float* __restrict__ bias)
{
    extern __shared__ __align__(16) char smk[];
    const uint32_t sbase = smem_u32(smk);

    const int tid  = threadIdx.x;
    const int lane = tid & 31;
    const int wid  = tid >> 5;
    const int bx   = blockIdx.x;
    const int by   = blockIdx.y;

    const int m0w = (wid & 3) * 32;
    const int n0w = (wid >> 2) * 64;
    const int g   = lane >> 2;
    const int tq  = lane & 3;

    float d[2][8][4];
#pragma unroll
    for (int i = 0; i < 2; i++)
#pragma unroll
        for (int j = 0; j < 8; j++)
#pragma unroll
            for (int q = 0; q < 4; q++) d[i][j][q] = 0.f;

    // copy mapping: row = tid>>1, 32-byte half = (tid&1)*32 (2 cp16 per array)
    const int r = tid >> 1;
    const int c32 = (tid & 1) * 32;
    const size_t a_row_bytes = ((size_t)(by * 128 + r) * KP) * 2 + c32;
    const size_t b_row_bytes = ((size_t)(bx * 128 + r) * KP) * 2 + c32;
    const char* pAh = (const char*)g_ah  + a_row_bytes;
    const char* pBh = (const char*)g_bhi + b_row_bytes;
    const char* pBl = (const char*)g_blo + b_row_bytes;
    const uint32_t s_off = (uint32_t)(r * SROW + c32);

    uint32_t a_off[2], b_off[4];
#pragma unroll
    for (int i = 0; i < 2; i++)
        a_off[i] = (uint32_t)((m0w + i * 16 + (lane & 15)) * SROW + (lane >> 4) * 16);
#pragma unroll
    for (int j2 = 0; j2 < 4; j2++)
        b_off[j2] = (uint32_t)((n0w + j2 * 16 + ((lane >> 4) * 8) + (lane & 7)) * SROW
                               + ((lane >> 3) & 1) * 16);

    // prologue: stages 0, 1
#pragma unroll
    for (int s = 0; s < 2; s++) {
        const uint32_t sb = sbase + s * K1_STAGE_BYTES;
        const size_t gk = (size_t)s * 64;    // 32 fp16 = 64 bytes per chunk
        cp16(sb + s_off,                      pAh + gk);
        cp16(sb + s_off + 16,                 pAh + gk + 16);
        cp16(sb + K1_ARR_BYTES + s_off,       pBh + gk);
        cp16(sb + K1_ARR_BYTES + s_off + 16,  pBh + gk + 16);
        cp16(sb + 2*K1_ARR_BYTES + s_off,     pBl + gk);
        cp16(sb + 2*K1_ARR_BYTES + s_off + 16,pBl + gk + 16);
        CP_COMMIT();
    }

    int buf = 0, nbuf = 2;
    for (int ic = 0; ic < NCHK2; ic++) {
        CP_WAIT1();          // stage ic complete
        __syncthreads();     // all warps done with stage ic-1's buffer

        {
            const int s = ic + 2;
            if (s < NCHK2) {
                const uint32_t sb = sbase + nbuf * K1_STAGE_BYTES;
                const size_t gk = (size_t)s * 64;
                cp16(sb + s_off,                      pAh + gk);
                cp16(sb + s_off + 16,                 pAh + gk + 16);
                cp16(sb + K1_ARR_BYTES + s_off,       pBh + gk);
                cp16(sb + K1_ARR_BYTES + s_off + 16,  pBh + gk + 16);
                cp16(sb + 2*K1_ARR_BYTES + s_off,     pBl + gk);
                cp16(sb + 2*K1_ARR_BYTES + s_off + 16,pBl + gk + 16);
            }
            CP_COMMIT();
        }

        const uint32_t stg = sbase + buf * K1_STAGE_BYTES;

#pragma unroll
        for (int sub = 0; sub < 2; sub++) {
            const uint32_t so = sub * 32;
            uint32_t ah[2][4];
#pragma unroll
            for (int i = 0; i < 2; i++)
                ldsm4(ah[i], stg + a_off[i] + so);

#pragma unroll
            for (int j2 = 0; j2 < 4; j2++) {
                uint32_t bh4[4], bl4[4];
                ldsm4(bh4, stg + K1_ARR_BYTES   + b_off[j2] + so);
                ldsm4(bl4, stg + 2*K1_ARR_BYTES + b_off[j2] + so);
#pragma unroll
                for (int jj = 0; jj < 2; jj++) {
                    const int j = j2 * 2 + jj;
                    uint32_t bhf[2] = {bh4[jj * 2], bh4[jj * 2 + 1]};
                    uint32_t blf[2] = {bl4[jj * 2], bl4[jj * 2 + 1]};
#pragma unroll
                    for (int i = 0; i < 2; i++) {
                        mma_f16(d[i][j], ah[i], bhf);
                        mma_f16(d[i][j], ah[i], blf);
                    }
                }
            }
        }

        buf = (buf + 1) % 3;
        nbuf = (nbuf + 1) % 3;
    }

#pragma unroll
    for (int j = 0; j < 8; j++) {
        const int col = bx * 128 + n0w + j * 8 + tq * 2;
        const float b0 = bias[col];
        const float b1 = bias[col + 1];
#pragma unroll
        for (int i = 0; i < 2; i++) {
            const int row = by * 128 + m0w + i * 16 + g;
            float2 v0 = make_float2(d[i][j][0] + b0, d[i][j][1] + b1);
            float2 v1 = make_float2(d[i][j][2] + b0, d[i][j][3] + b1);
            *(float2*)(g_xw + (size_t)row * NG + col)       = v0;
            *(float2*)(g_xw + (size_t)(row + 8) * NG + col) = v1;
        }
    }
}

// ---------------------------------------------------------------------------
// K2: peephole LSTM — 32 clusters x 4 CTAs, 4 batches/cluster,
// LANE-LEVEL k-split with conflict-free layouts (R14 root causes fixed):
//   warp w owns units [w*8, w*8+8); lane = (u8 = lane>>2, kq = lane&3).
//   Weights interleaved wsm[kk][ul][kq] -> warp reads 512B CONTIGUOUS per k.
//   h blocks padded to 2080 B per kq -> 4 kq h-lines in distinct bank quarters.
//   48 k/quarter smem (196 KB) + 16 k/quarter persistent registers.
//   Reduction over kq = 2 shfl_xor rounds; lane kq doubles as batch for the
//   gate phase. No __syncthreads in the step loop; split cluster barrier.
// ---------------------------------------------------------------------------
#define K2_CLU   4
#define K2_BATCH 4
#define K2_KS    48
#define K2_KR    16
#define K2_WSB   (K2_KS * 64 * 4 * 16)           // 196608
#define K2_HBLK  2080                            // 64 units * 4 b * 8 + 32 pad
#define K2_HBUF  (4 * K2_HBLK)                   // 8320 per buffer
#define K2_H2SZ  (2 * K2_HBUF)                   // 16640
#define K2_SMEM  (K2_WSB + K2_H2SZ)              // 213248

__global__ __launch_bounds__(256, 1) __cluster_dims__(K2_CLU, 1, 1)
void lstm_shfl_kernel(const float*  __restrict__ xw,
                      const float4* __restrict__ rw,
                      const float*  __restrict__ wci_p,
                      const float*  __restrict__ wcf_p,
                      const float*  __restrict__ wco_p,
                      float* __restrict__ hs)
{
    extern __shared__ __align__(16) char sm2[];
    char* wsm = sm2;                       // [kk][ul][kq] ull2
    char* h2  = sm2 + K2_WSB;              // [2][4 kq-blk pad 2080][64 u][4 b] dup-ull

    const int tid = threadIdx.x;
    uint32_t rank;
    asm("mov.u32 %0, %%cluster_ctarank;" : "=r"(rank));
    const int cl = blockIdx.x >> 2;
    const int b0 = cl * K2_BATCH;

    const int w    = tid >> 5;
    const int lane = tid & 31;
    const int u8   = lane >> 2;          // unit within warp
    const int kq   = lane & 3;           // k-quarter == owned batch
    const int ul   = w * 8 + u8;         // unit within CTA (0..63)
    const int uc   = (int)rank * 64 + ul;
    const int cb   = kq;

    // stage smem weights: wsm[(kk*256 + ul*4 + kq)*16] = rw[(kq*64+kk)*256 + rank*64 + ul]
    for (int idx = tid; idx < K2_KS * 64 * 4; idx += 256) {
        int kq_ = idx & 3;
        int ul_ = (idx >> 2) & 63;
        int kk_ = idx >> 8;
        *(float4*)(wsm + (size_t)idx * 16) =
            rw[((kq_ * 64 + kk_) << 8) + (int)rank * 64 + ul_];
    }
    // zero both h buffers (16640 B = 2080 ull)
    for (int i = tid; i < K2_H2SZ / 8; i += 256)
        *(unsigned long long*)(h2 + (size_t)i * 8) = 0ull;

    const float wci = wci_p[uc];
    const float wcf = wcf_p[uc];
    const float wco = wco_p[uc];

    // DSMEM addresses of this cell's h slot (buffer 0) in all 4 CTAs
    uint32_t rem[K2_CLU];
    {
        uint32_t l0 = smem_u32(h2) + (uint32_t)((uc >> 6) * K2_HBLK
                                                + ((uc & 63) * 4 + cb) * 8);
#pragma unroll
        for (int r2 = 0; r2 < K2_CLU; r2++)
            asm("mapa.shared::cluster.u32 %0, %1, %2;"
                : "=r"(rem[r2]) : "r"(l0), "r"(r2));
    }

    // persistent register weights: k = kq*64 + 48 + j for unit uc
    ulonglong2 wper[K2_KR];
#pragma unroll
    for (int j = 0; j < K2_KR; j++)
        wper[j] = *(const ulonglong2*)((const char*)(rw + (size_t)(kq * 64 + K2_KS + j) * HH + uc));

    __syncthreads();
    asm volatile("barrier.cluster.arrive.aligned;" ::: "memory");
    asm volatile("barrier.cluster.wait.aligned;"   ::: "memory");

    const char* wp_s = wsm + (size_t)(ul * 4 + kq) * 16;   // k-stride 4096 B
    const float* xc = xw + (size_t)(b0 + cb) * TT * NG;
    float* hc = hs + (size_t)(b0 + cb) * TT * HH + uc;

    float cstate = 0.f;

    for (int t = 0; t < TT; t++) {
        const int rb = t & 1;

        // this step's gate inputs — independent of h(t), issued before wait
        float xv0 = xc[uc];
        float xv1 = xc[HH + uc];
        float xv2 = xc[2 * HH + uc];
        float xv3 = xc[3 * HH + uc];

        if (t > 0)
            asm volatile("barrier.cluster.wait.aligned;" ::: "memory");

        unsigned long long aif[4], aco[4];
#pragma unroll
        for (int b2 = 0; b2 < 4; b2++) { aif[b2] = 0ull; aco[b2] = 0ull; }

        const char* hq = h2 + rb * K2_HBUF + kq * K2_HBLK;

        // smem tier: k = kq*64 + [0,48)
#pragma unroll 8
        for (int kk = 0; kk < K2_KS; kk++) {
            ulonglong2 wv = *(const ulonglong2*)(wp_s + (size_t)kk * 4096);
            const char* hh = hq + kk * 32;
            ulonglong2 h01 = *(const ulonglong2*)(hh);
            ulonglong2 h23 = *(const ulonglong2*)(hh + 16);
            ffma2(aif[0], wv.x, h01.x); ffma2(aco[0], wv.y, h01.x);
            ffma2(aif[1], wv.x, h01.y); ffma2(aco[1], wv.y, h01.y);
            ffma2(aif[2], wv.x, h23.x); ffma2(aco[2], wv.y, h23.x);
            ffma2(aif[3], wv.x, h23.y); ffma2(aco[3], wv.y, h23.y);
        }
        // register tier: k = kq*64 + [48,64)
#pragma unroll
        for (int j = 0; j < K2_KR; j++) {
            ulonglong2 wv = wper[j];
            const char* hh = hq + (K2_KS + j) * 32;
            ulonglong2 h01 = *(const ulonglong2*)(hh);
            ulonglong2 h23 = *(const ulonglong2*)(hh + 16);
            ffma2(aif[0], wv.x, h01.x); ffma2(aco[0], wv.y, h01.x);
            ffma2(aif[1], wv.x, h01.y); ffma2(aco[1], wv.y, h01.y);
            ffma2(aif[2], wv.x, h23.x); ffma2(aco[2], wv.y, h23.x);
            ffma2(aif[3], wv.x, h23.y); ffma2(aco[3], wv.y, h23.y);
        }

        // reduce over the 4 k-quarters (lanes differing in bits 0-1)
#pragma unroll
        for (int b2 = 0; b2 < 4; b2++) {
            aif[b2] = addx2(aif[b2], shflx2(aif[b2], 1));
            aif[b2] = addx2(aif[b2], shflx2(aif[b2], 2));
            aco[b2] = addx2(aco[b2], shflx2(aco[b2], 1));
            aco[b2] = addx2(aco[b2], shflx2(aco[b2], 2));
        }

        // gate math for this lane's cell (unit uc, batch cb = kq)
        float zi = lof(aif[cb]), zf = hif(aif[cb]);
        float zc = lof(aco[cb]), zo = hif(aco[cb]);

        float ig = fsig(zi + xv0 + cstate * wci);
        float fg = fsig(zf + xv1 + cstate * wcf);
        float cn = fg * cstate + ig * ftanh(zc + xv2);
        float og = fsig(zo + xv3 + cn * wco);
        float hn = og * ftanh(cn);
        cstate = cn;

        // publish h (dup pair) into write buffer of all 4 CTAs
        unsigned long long hdup;
        asm("mov.b64 %0, {%1, %1};" : "=l"(hdup) : "r"(__float_as_uint(hn)));
        const uint32_t wboff = (uint32_t)((rb ^ 1) * K2_HBUF);
#pragma unroll
        for (int r2 = 0; r2 < K2_CLU; r2++)
            asm volatile("st.shared::cluster.b64 [%0], %1;"
                         :: "r"(rem[r2] + wboff), "l"(hdup) : "memory");

        hc[0] = hn;
        hc += HH;
        xc += NG;

        asm volatile("barrier.cluster.arrive.aligned;" ::: "memory");
    }
    asm volatile("barrier.cluster.wait.aligned;" ::: "memory");
}

// ---------------------------------------------------------------------------
// K3: BN(inference) -> tanh -> dense head.
// ---------------------------------------------------------------------------
__global__ __launch_bounds__(256)
void head_kernel(const float* __restrict__ hs,
                 const float* __restrict__ gamma,
                 const float* __restrict__ beta,
                 const float* __restrict__ mean,
                 const float* __restrict__ var,
                 const float* __restrict__ fc,
                 float* __restrict__ out)
{
    const int warp = (blockIdx.x * blockDim.x + threadIdx.x) >> 5;
    const int lane = threadIdx.x & 31;
    if (warp >= BB * TT) return;

    const float* hrow = hs + (size_t)warp * HH;
    float acc[CC];
#pragma unroll
    for (int c = 0; c < CC; c++) acc[c] = 0.f;

#pragma unroll
    for (int kk = 0; kk < HH / 32; kk++) {
        int k = kk * 32 + lane;
        float s = rsqrtf(var[k] + BN_EPS) * gamma[k];
        float v = tanhf((hrow[k] - mean[k]) * s + beta[k]);
#pragma unroll
        for (int c = 0; c < CC; c++)
            acc[c] += v * fc[k * CC + c];
    }
#pragma unroll
    for (int c = 0; c < CC; c++) {
#pragma unroll
        for (int off = 16; off > 0; off >>= 1)
            acc[c] += __shfl_xor_sync(0xffffffffu, acc[c], off);
    }
    if (lane == 0) {
        float* orow = out + (size_t)warp * CC;
#pragma unroll
        for (int c = 0; c < CC; c++) orow[c] = acc[c];
    }
}

// ---------------------------------------------------------------------------
extern "C" void kernel_launch(void* const* d_in, const int* in_sizes, int n_in,
                              void* d_out, int out_size)
{
    const float* x      = (const float*)d_in[0];
    const float* kernel = (const float*)d_in[1];
    const float* rec    = (const float*)d_in[2];
    const float* bias   = (const float*)d_in[3];
    const float* w_ci   = (const float*)d_in[4];
    const float* w_cf   = (const float*)d_in[5];
    const float* w_co   = (const float*)d_in[6];
    const float* gamma  = (const float*)d_in[7];
    const float* beta   = (const float*)d_in[8];
    const float* mmean  = (const float*)d_in[9];
    const float* mvar   = (const float*)d_in[10];
    const float* fc_w   = (const float*)d_in[11];
    float* out = (float*)d_out;

    float*  xw_p;
    float*  hs_p;
    float4* rw_p;
    cudaGetSymbolAddress((void**)&xw_p, g_xw);
    cudaGetSymbolAddress((void**)&hs_p, g_hs);
    cudaGetSymbolAddress((void**)&rw_p, g_rw);

    cudaFuncSetAttribute(gemm_mma_kernel,
                         cudaFuncAttributeMaxDynamicSharedMemorySize, K1_SMEM);
    cudaFuncSetAttribute(lstm_shfl_kernel,
                         cudaFuncAttributeMaxDynamicSharedMemorySize, K2_SMEM);

    // K0: packing
    pack_rec_kernel<<<(HH * HH + 255) / 256, 256>>>(rec, rw_p);
    pack_b_kernel<<<((size_t)NG * KP + 255) / 256, 256>>>(kernel);
    pack_a_kernel<<<(unsigned)(((size_t)BB * TT * KP + 255) / 256), 256>>>(x);

    // K1: BK=32 cp.async-pipelined fp16x2 HMMA GEMM
    dim3 g1(NG / 128, (BB * TT) / 128);
    gemm_mma_kernel<<<g1, 256, K1_SMEM>>>(bias);

    // K2: recurrence — lane-level k-split, shuffle reduce, no per-step sync
    lstm_shfl_kernel<<<(BB / K2_BATCH) * K2_CLU, 256, K2_SMEM>>>(
        xw_p, rw_p, w_ci, w_cf, w_co, hs_p);

    // K3: head
    int rows = BB * TT;
    head_kernel<<<(rows * 32 + 255) / 256, 256>>>(hs_p, gamma, beta, mmean, mvar, fc_w, out);
}